// round 14
// baseline (speedup 1.0000x reference)
#include <cuda_runtime.h>
#include <cuda_fp16.h>
#include <cstdint>

// EdgeBlock: out[e,:] = W @ concat(edges[e], nodes[recv[e]], nodes[send[e]]) + b
// E=500000, NODE_D=EDGE_D=128, IN_D=384, W [128,384] row-major, out [E,128] f32.
// R14: single-pass fp16 mma (validated rel_err 2.9e-4). 3 full-width chunks
//      (3 barriers/tile), uniform fp16 LDSM compute path; edges converted to
//      fp16 during staging; nodes cp.async from pre-converted fp16 table.

#define IN_D    384
#define OUT_D   128
#define TM      128
#define NCHUNK  3
#define NK16    24
#define THREADS 256
#define N_NODES_MAX 50000

#define STRH    272                  // bytes per fp16 buffer row (128 + 8 pad halves)
#define BUFSZ   (TM * STRH)          // 34816 per stage
#define BIAS_OFF (3 * BUFSZ)         // 104448
#define SM_TOTAL (BIAS_OFF + 512)    // 104960

__device__ __forceinline__ uint32_t smem_u32(const void* p) {
    uint32_t a;
    asm("{ .reg .u64 t; cvta.to.shared.u64 t, %1; cvt.u32.u64 %0, t; }" : "=r"(a) : "l"(p));
    return a;
}
__device__ __forceinline__ void cp_async16(uint32_t dst, const void* src) {
    asm volatile("cp.async.cg.shared.global [%0], [%1], 16;"
                 :: "r"(dst), "l"(src) : "memory");
}
#define CP_COMMIT() asm volatile("cp.async.commit_group;" ::: "memory")
template <int N>
__device__ __forceinline__ void cp_wait() {
    asm volatile("cp.async.wait_group %0;" :: "n"(N) : "memory");
}
__device__ __forceinline__ void ldsm_x4(uint32_t& r0, uint32_t& r1, uint32_t& r2, uint32_t& r3,
                                        uint32_t addr) {
    asm volatile("ldmatrix.sync.aligned.m8n8.x4.shared.b16 {%0,%1,%2,%3}, [%4];"
                 : "=r"(r0), "=r"(r1), "=r"(r2), "=r"(r3) : "r"(addr));
}
__device__ __forceinline__ void mma16816(float& c0, float& c1, float& c2, float& c3,
                                         uint32_t a0, uint32_t a1, uint32_t a2, uint32_t a3,
                                         uint32_t b0, uint32_t b1) {
    asm volatile("mma.sync.aligned.m16n8k16.row.col.f32.f16.f16.f32 "
                 "{%0,%1,%2,%3}, {%4,%5,%6,%7}, {%8,%9}, {%0,%1,%2,%3};"
                 : "+f"(c0), "+f"(c1), "+f"(c2), "+f"(c3)
                 : "r"(a0), "r"(a1), "r"(a2), "r"(a3), "r"(b0), "r"(b1));
}
__device__ __forceinline__ uint32_t f16x2(float x, float y) {
    uint32_t r;
    asm("cvt.rn.f16x2.f32 %0, %1, %2;" : "=r"(r) : "f"(y), "f"(x));
    return r;
}

// ---- W pre-packed as mma B-fragments: [k16][n8][reg][lane] -> uint32 f16x2 ----
__device__ __align__(16) uint32_t g_Wfrag[NK16 * 16 * 2 * 32];
// ---- nodes pre-converted to fp16, [node][128] row-major ----
__device__ __align__(16) __half g_Nf16[(size_t)N_NODES_MAX * 128];

__global__ void prep_W_kernel(const float* __restrict__ W) {
    int i = blockIdx.x * blockDim.x + threadIdx.x;
    if (i >= NK16 * 16 * 2 * 32) return;
    int lane = i & 31;
    int reg  = (i >> 5) & 1;
    int n8   = (i >> 6) & 15;
    int k16  = i >> 10;
    int n_g  = n8 * 8 + (lane >> 2);
    int k_g  = k16 * 16 + (lane & 3) * 2 + reg * 8;
    __half2 hv(__float2half_rn(W[n_g * IN_D + k_g]),
               __float2half_rn(W[n_g * IN_D + k_g + 1]));
    g_Wfrag[i] = *reinterpret_cast<uint32_t*>(&hv);
}

__global__ void prep_nodes_kernel(const float* __restrict__ nodes, int total4) {
    int i = blockIdx.x * blockDim.x + threadIdx.x;
    if (i >= total4) return;
    float4 v = reinterpret_cast<const float4*>(nodes)[i];
    __half h[4] = {__float2half_rn(v.x), __float2half_rn(v.y),
                   __float2half_rn(v.z), __float2half_rn(v.w)};
    *reinterpret_cast<uint2*>(g_Nf16 + i * 4) = *reinterpret_cast<uint2*>(h);
}

__global__ void __launch_bounds__(THREADS, 2)
edgeblock_mma_kernel(const float* __restrict__ edges,
                     const int* __restrict__ recv,
                     const int* __restrict__ send,
                     const float* __restrict__ bias,
                     float* __restrict__ out,
                     int E)
{
    extern __shared__ char smem[];
    const uint32_t sm = smem_u32(smem);
    const int t = threadIdx.x;
    const int lane = t & 31, wid = t >> 5;
    const int e0 = blockIdx.x * TM;

    const int m_base = (wid & 1) * 64;
    const int n8base = (wid >> 1) * 4;

    float* Bs = (float*)(smem + BIAS_OFF);
    if (t < OUT_D) Bs[t] = bias[t];

    // ---- edge staging: LDG fp32 -> cvt fp16 -> STS (buffer 0) ----
    auto stage_edge = [&]() {
        const int sr = t >> 1, sh = t & 1;          // row, 64-col half
        int e = e0 + sr;
        const float* src = edges + (size_t)(e < E ? e : 0) * 128 + sh * 64;
        const uint32_t dst = sm + (uint32_t)sr * STRH + sh * 128;
#pragma unroll
        for (int i = 0; i < 8; ++i) {
            float4 fa = *reinterpret_cast<const float4*>(src + i * 8);
            float4 fb = *reinterpret_cast<const float4*>(src + i * 8 + 4);
            uint4 h;
            h.x = f16x2(fa.x, fa.y);
            h.y = f16x2(fa.z, fa.w);
            h.z = f16x2(fb.x, fb.y);
            h.w = f16x2(fb.z, fb.w);
            *reinterpret_cast<uint4*>(smem + (dst - sm) + i * 16) = h;
        }
    };
    // ---- node staging: cp.async fp16 rows into buffer b ----
    auto stage_node = [&](const int* __restrict__ idxs, int b) {
        const uint32_t buf = sm + b * BUFSZ;
#pragma unroll
        for (int i = 0; i < 8; ++i) {
            int idx = t + i * THREADS;               // 0..2047
            int row = idx >> 4, p = idx & 15;        // 16 x 16B segs per row
            int e = e0 + row;
            int node = (e < E) ? __ldg(&idxs[e]) : 0;
            const char* srcp = (const char*)g_Nf16 + (size_t)node * 256 + p * 16;
            cp_async16(buf + row * STRH + p * 16, srcp);
        }
        CP_COMMIT();
    };

    float acc[4][4][4];
#pragma unroll
    for (int i = 0; i < 4; ++i)
#pragma unroll
        for (int j = 0; j < 4; ++j)
#pragma unroll
            for (int k = 0; k < 4; ++k) acc[i][j][k] = 0.f;

    const int gq = lane >> 2, t4 = lane & 3;
    const int lr = lane & 7, g4 = lane >> 3;
    const uint32_t abase = (uint32_t)(m_base + lr + (g4 & 1) * 8) * STRH + (g4 >> 1) * 16;

    // ---- uniform compute: 8 k16-steps from fp16 buffer b ----
    auto compute = [&](int c, int b) {
        const uint32_t hb = sm + b * BUFSZ + abase;
#pragma unroll
        for (int kk = 0; kk < 8; ++kk) {
            const int k16g = c * 8 + kk;
            uint32_t bw[4][2];
#pragma unroll
            for (int tn = 0; tn < 4; ++tn)
#pragma unroll
                for (int rg = 0; rg < 2; ++rg)
                    bw[tn][rg] = __ldg(&g_Wfrag[(((k16g * 16) + n8base + tn) * 2 + rg) * 32 + lane]);
#pragma unroll
            for (int tm = 0; tm < 4; ++tm) {
                uint32_t a[4];
                ldsm_x4(a[0], a[1], a[2], a[3], hb + tm * 16 * STRH + kk * 32);
#pragma unroll
                for (int tn = 0; tn < 4; ++tn)
                    mma16816(acc[tm][tn][0], acc[tm][tn][1], acc[tm][tn][2], acc[tm][tn][3],
                             a[0], a[1], a[2], a[3], bw[tn][0], bw[tn][1]);
            }
        }
    };

    // ---- pipeline: 3 chunks, 3 barriers ----
    stage_edge();                 // buf0 (synchronous STS)
    stage_node(recv, 1);          // buf1, cp group A
    __syncthreads();              // buf0 + bias visible
    compute(0, 0);
    stage_node(send, 2);          // buf2, cp group B
    cp_wait<1>();                 // group A complete
    __syncthreads();
    compute(1, 1);
    cp_wait<0>();                 // group B complete
    __syncthreads();
    compute(2, 2);

    // ---- epilogue ----
#pragma unroll
    for (int tm = 0; tm < 4; ++tm) {
        int r0 = e0 + m_base + tm * 16 + gq;
        int r1 = r0 + 8;
#pragma unroll
        for (int tn = 0; tn < 4; ++tn) {
            int cbase = n8base * 8 + tn * 8 + t4 * 2;
            float b0 = Bs[cbase], b1 = Bs[cbase + 1];
            if (r0 < E) {
                float2 v = make_float2(acc[tm][tn][0] + b0, acc[tm][tn][1] + b1);
                *reinterpret_cast<float2*>(out + (size_t)r0 * OUT_D + cbase) = v;
            }
            if (r1 < E) {
                float2 v = make_float2(acc[tm][tn][2] + b0, acc[tm][tn][3] + b1);
                *reinterpret_cast<float2*>(out + (size_t)r1 * OUT_D + cbase) = v;
            }
        }
    }
}

extern "C" void kernel_launch(void* const* d_in, const int* in_sizes, int n_in,
                              void* d_out, int out_size)
{
    const float* nodes = (const float*)d_in[0];
    const float* edges = (const float*)d_in[1];
    const int*   recv  = (const int*)d_in[2];
    const int*   send  = (const int*)d_in[3];
    const float* W     = (const float*)d_in[4];
    const float* bias  = (const float*)d_in[5];
    float*       out   = (float*)d_out;
    int E = in_sizes[2];
    int n_node_f = in_sizes[0];

    cudaFuncSetAttribute(edgeblock_mma_kernel,
                         cudaFuncAttributeMaxDynamicSharedMemorySize, SM_TOTAL);

    prep_W_kernel<<<(NK16 * 16 * 2 * 32 + 255) / 256, 256>>>(W);
    int total4 = n_node_f / 4;
    prep_nodes_kernel<<<(total4 + 255) / 256, 256>>>(nodes, total4);
    int grid = (E + TM - 1) / TM;
    edgeblock_mma_kernel<<<grid, THREADS, SM_TOTAL>>>(edges, recv, send, bias, out, E);
}

// round 17
// speedup vs baseline: 1.2712x; 1.2712x over previous
#include <cuda_runtime.h>
#include <cuda_fp16.h>
#include <cstdint>

// EdgeBlock: out[e,:] = W @ concat(edges[e], nodes[recv[e]], nodes[send[e]]) + b
// E=500000, NODE_D=EDGE_D=128, IN_D=384, W [128,384] row-major, out [E,128] f32.
// R15: single-pass fp16 mma (validated rel_err 2.93e-4). R13 6-chunk pipeline,
//      but chunk order recv,send,edges; edges staged via register-pipelined
//      LDG->cvt->STS overlapped under node-chunk MMA; ALL compute = LDSM path.

#define IN_D    384
#define OUT_D   128
#define TM      128
#define NCHUNK  6
#define NK16    24
#define THREADS 256
#define N_NODES_MAX 50000

#define STRH    144                  // bytes per fp16 row (64 halves + 8 pad)
#define BUFSZ   (TM * STRH)          // 18432 per stage
#define RIDX_OFF (3 * BUFSZ)         // 55296
#define SIDX_OFF (RIDX_OFF + 512)
#define BIAS_OFF (SIDX_OFF + 512)
#define SM_TOTAL (BIAS_OFF + 512)    // 56832

__device__ __forceinline__ uint32_t smem_u32(const void* p) {
    uint32_t a;
    asm("{ .reg .u64 t; cvta.to.shared.u64 t, %1; cvt.u32.u64 %0, t; }" : "=r"(a) : "l"(p));
    return a;
}
__device__ __forceinline__ void cp_async16(uint32_t dst, const void* src) {
    asm volatile("cp.async.cg.shared.global [%0], [%1], 16;"
                 :: "r"(dst), "l"(src) : "memory");
}
#define CP_COMMIT() asm volatile("cp.async.commit_group;" ::: "memory")
template <int N>
__device__ __forceinline__ void cp_wait() {
    asm volatile("cp.async.wait_group %0;" :: "n"(N) : "memory");
}
__device__ __forceinline__ void ldsm_x4(uint32_t& r0, uint32_t& r1, uint32_t& r2, uint32_t& r3,
                                        uint32_t addr) {
    asm volatile("ldmatrix.sync.aligned.m8n8.x4.shared.b16 {%0,%1,%2,%3}, [%4];"
                 : "=r"(r0), "=r"(r1), "=r"(r2), "=r"(r3) : "r"(addr));
}
__device__ __forceinline__ void mma16816(float& c0, float& c1, float& c2, float& c3,
                                         uint32_t a0, uint32_t a1, uint32_t a2, uint32_t a3,
                                         uint32_t b0, uint32_t b1) {
    asm volatile("mma.sync.aligned.m16n8k16.row.col.f32.f16.f16.f32 "
                 "{%0,%1,%2,%3}, {%4,%5,%6,%7}, {%8,%9}, {%0,%1,%2,%3};"
                 : "+f"(c0), "+f"(c1), "+f"(c2), "+f"(c3)
                 : "r"(a0), "r"(a1), "r"(a2), "r"(a3), "r"(b0), "r"(b1));
}
__device__ __forceinline__ uint32_t f16x2(float x, float y) {
    uint32_t r;
    asm("cvt.rn.f16x2.f32 %0, %1, %2;" : "=r"(r) : "f"(y), "f"(x));
    return r;
}

// ---- W pre-packed as mma B-fragments: [k16][n8][reg][lane] -> uint32 f16x2 ----
__device__ __align__(16) uint32_t g_Wfrag[NK16 * 16 * 2 * 32];
// ---- nodes pre-converted to fp16, [node][128] row-major ----
__device__ __align__(16) __half g_Nf16[(size_t)N_NODES_MAX * 128];

__global__ void prep_W_kernel(const float* __restrict__ W) {
    int i = blockIdx.x * blockDim.x + threadIdx.x;
    if (i >= NK16 * 16 * 2 * 32) return;
    int lane = i & 31;
    int reg  = (i >> 5) & 1;
    int n8   = (i >> 6) & 15;
    int k16  = i >> 10;
    int n_g  = n8 * 8 + (lane >> 2);
    int k_g  = k16 * 16 + (lane & 3) * 2 + reg * 8;
    __half2 hv(__float2half_rn(W[n_g * IN_D + k_g]),
               __float2half_rn(W[n_g * IN_D + k_g + 1]));
    g_Wfrag[i] = *reinterpret_cast<uint32_t*>(&hv);
}

__global__ void prep_nodes_kernel(const float* __restrict__ nodes, int total4) {
    int i = blockIdx.x * blockDim.x + threadIdx.x;
    if (i >= total4) return;
    float4 v = reinterpret_cast<const float4*>(nodes)[i];
    __half h[4] = {__float2half_rn(v.x), __float2half_rn(v.y),
                   __float2half_rn(v.z), __float2half_rn(v.w)};
    *reinterpret_cast<uint2*>(g_Nf16 + i * 4) = *reinterpret_cast<uint2*>(h);
}

// chunk -> global k16 base (concat order: edges[0:8], recv[8:16], send[16:24])
__device__ __constant__ int c_k16base[NCHUNK] = {8, 12, 16, 20, 0, 4};

__global__ void __launch_bounds__(THREADS, 2)
edgeblock_mma_kernel(const float* __restrict__ edges,
                     const int* __restrict__ recv,
                     const int* __restrict__ send,
                     const float* __restrict__ bias,
                     float* __restrict__ out,
                     int E)
{
    extern __shared__ char smem[];
    const uint32_t sm = smem_u32(smem);
    const int t = threadIdx.x;
    const int lane = t & 31, wid = t >> 5;
    const int e0 = blockIdx.x * TM;

    const int m_base = (wid & 1) * 64;
    const int n8base = (wid >> 1) * 4;

    int* Ridx = (int*)(smem + RIDX_OFF);
    int* Sidx = (int*)(smem + SIDX_OFF);
    float* Bs = (float*)(smem + BIAS_OFF);
    if (t < TM) {
        int e = e0 + t;
        Ridx[t] = (e < E) ? recv[e] : 0;
        Sidx[t] = (e < E) ? send[e] : 0;
        Bs[t] = bias[t];
    }
    __syncthreads();

    // ---- node staging: cp.async fp16 64-col chunk into buffer b ----
    // chunk c: 0,1 = recv cols (c&1)*64 ; 2,3 = send cols (c&1)*64
    auto stage_node = [&](int c, int b) {
        const uint32_t buf = sm + b * BUFSZ;
        const int coff = (c & 1) * 64;
        const int* idxs = (c < 2) ? Ridx : Sidx;
#pragma unroll
        for (int i = 0; i < 4; ++i) {
            int idx = t + i * THREADS;
            int row = idx >> 3, p = idx & 7;         // 8 x 16B segs per row
            int node = idxs[row];
            const char* srcp = (const char*)g_Nf16
                             + ((size_t)node * 128 + coff) * 2 + p * 16;
            cp_async16(buf + row * STRH + p * 16, srcp);
        }
        CP_COMMIT();
    };

    // ---- edge staging: register-pipelined LDG -> cvt (held) -> STS ----
    const int sr = t >> 1, sh = t & 1;               // row, 32-col half of chunk
    const int e_row = e0 + sr;
    uint32_t ereg[16];
    auto ldg_edge = [&](int c) {                     // c = 4 or 5
        const float4* p = reinterpret_cast<const float4*>(
            edges + (size_t)(e_row < E ? e_row : 0) * 128 + (c - 4) * 64 + sh * 32);
#pragma unroll
        for (int i = 0; i < 4; ++i) {
            float4 fa = p[2 * i];
            float4 fb = p[2 * i + 1];
            ereg[4 * i + 0] = f16x2(fa.x, fa.y);
            ereg[4 * i + 1] = f16x2(fa.z, fa.w);
            ereg[4 * i + 2] = f16x2(fb.x, fb.y);
            ereg[4 * i + 3] = f16x2(fb.z, fb.w);
        }
    };
    auto sts_edge = [&](int b) {
        const uint32_t dst = (uint32_t)(b * BUFSZ) + (uint32_t)sr * STRH + sh * 64;
#pragma unroll
        for (int i = 0; i < 4; ++i)
            *reinterpret_cast<uint4*>(smem + dst + i * 16) =
                *reinterpret_cast<uint4*>(&ereg[4 * i]);
    };

    float acc[4][4][4];
#pragma unroll
    for (int i = 0; i < 4; ++i)
#pragma unroll
        for (int j = 0; j < 4; ++j)
#pragma unroll
            for (int k = 0; k < 4; ++k) acc[i][j][k] = 0.f;

    const int gq = lane >> 2, t4 = lane & 3;
    const int lr = lane & 7, g4 = lane >> 3;
    const uint32_t abase = (uint32_t)(m_base + lr + (g4 & 1) * 8) * STRH + (g4 >> 1) * 16;

    // ---- uniform compute: 4 k16-steps from fp16 buffer b ----
    auto compute = [&](int c, int b) {
        const uint32_t hb = sm + b * BUFSZ + abase;
        const int kb = c_k16base[c];
#pragma unroll
        for (int kk = 0; kk < 4; ++kk) {
            const int k16g = kb + kk;
            uint32_t bw[4][2];
#pragma unroll
            for (int tn = 0; tn < 4; ++tn)
#pragma unroll
                for (int rg = 0; rg < 2; ++rg)
                    bw[tn][rg] = __ldg(&g_Wfrag[(((k16g * 16) + n8base + tn) * 2 + rg) * 32 + lane]);
#pragma unroll
            for (int tm = 0; tm < 4; ++tm) {
                uint32_t a[4];
                ldsm_x4(a[0], a[1], a[2], a[3], hb + tm * 16 * STRH + kk * 32);
#pragma unroll
                for (int tn = 0; tn < 4; ++tn)
                    mma16816(acc[tm][tn][0], acc[tm][tn][1], acc[tm][tn][2], acc[tm][tn][3],
                             a[0], a[1], a[2], a[3], bw[tn][0], bw[tn][1]);
            }
        }
    };

    // ---- pipeline ----
    // chunks: 0,1 recv (cp) ; 2,3 send (cp) ; 4,5 edges (reg-pipelined)
    stage_node(0, 0);                 // group G0
    stage_node(1, 1);                 // G1
    cp_wait<1>(); __syncthreads();
    compute(0, 0); stage_node(2, 2);  // G2
    cp_wait<1>(); __syncthreads();
    compute(1, 1); stage_node(3, 0);  // G3
    cp_wait<1>(); __syncthreads();
    ldg_edge(4);                      // LDG latency hides under compute(2)
    compute(2, 2); sts_edge(1);
    cp_wait<0>(); __syncthreads();
    ldg_edge(5);                      // hides under compute(3)
    compute(3, 0); sts_edge(2);
    __syncthreads();
    compute(4, 1);
    __syncthreads();
    compute(5, 2);

    // ---- epilogue ----
#pragma unroll
    for (int tm = 0; tm < 4; ++tm) {
        int r0 = e0 + m_base + tm * 16 + gq;
        int r1 = r0 + 8;
#pragma unroll
        for (int tn = 0; tn < 4; ++tn) {
            int cbase = n8base * 8 + tn * 8 + t4 * 2;
            float b0 = Bs[cbase], b1 = Bs[cbase + 1];
            if (r0 < E) {
                float2 v = make_float2(acc[tm][tn][0] + b0, acc[tm][tn][1] + b1);
                *reinterpret_cast<float2*>(out + (size_t)r0 * OUT_D + cbase) = v;
            }
            if (r1 < E) {
                float2 v = make_float2(acc[tm][tn][2] + b0, acc[tm][tn][3] + b1);
                *reinterpret_cast<float2*>(out + (size_t)r1 * OUT_D + cbase) = v;
            }
        }
    }
}

extern "C" void kernel_launch(void* const* d_in, const int* in_sizes, int n_in,
                              void* d_out, int out_size)
{
    const float* nodes = (const float*)d_in[0];
    const float* edges = (const float*)d_in[1];
    const int*   recv  = (const int*)d_in[2];
    const int*   send  = (const int*)d_in[3];
    const float* W     = (const float*)d_in[4];
    const float* bias  = (const float*)d_in[5];
    float*       out   = (float*)d_out;
    int E = in_sizes[2];
    int n_node_f = in_sizes[0];

    cudaFuncSetAttribute(edgeblock_mma_kernel,
                         cudaFuncAttributeMaxDynamicSharedMemorySize, SM_TOTAL);

    prep_W_kernel<<<(NK16 * 16 * 2 * 32 + 255) / 256, 256>>>(W);
    int total4 = n_node_f / 4;
    prep_nodes_kernel<<<(total4 + 255) / 256, 256>>>(nodes, total4);
    int grid = (E + TM - 1) / TM;
    edgeblock_mma_kernel<<<grid, THREADS, SM_TOTAL>>>(edges, recv, send, bias, out, E);
}